// round 7
// baseline (speedup 1.0000x reference)
#include <cuda_runtime.h>
#include <cstdint>

#define N_ROWS 16384
#define FEATS  512
#define HID    256
#define CLS    64
#define NITER  10

// ---------------- scratch (no allocations allowed) ----------------
__device__ float g_W[FEATS * CLS];        // W1 @ W2
__device__ float g_bias[CLS];             // b1 @ W2 + b2
__device__ float g_Z0[N_ROWS * CLS];      // MLP output (fp32 alpha term)
__device__ float g_Zfinal[N_ROWS * CLS];  // final-iteration result
__device__ uint32_t g_adj32[(size_t)N_ROWS * N_ROWS];  // adj pre-rounded to tf32 bits
__device__ uint32_t g_ZT[2][CLS * N_ROWS];             // Z^T [class][node], tf32 bits

__device__ __forceinline__ uint32_t f2tf32(float f) {
    uint32_t u;
    asm volatile("cvt.rna.tf32.f32 %0, %1;\n" : "=r"(u) : "f"(f));
    return u;
}

// ---------------- kernel 1: collapse the MLP ----------------
__global__ void fuse_w_kernel(const float* __restrict__ W1,
                              const float* __restrict__ b1,
                              const float* __restrict__ W2,
                              const float* __restrict__ b2) {
    int idx = blockIdx.x * blockDim.x + threadIdx.x;
    if (idx < FEATS * CLS) {
        int f = idx / CLS, c = idx % CLS;
        float s = 0.f;
        #pragma unroll 8
        for (int k = 0; k < HID; k++) s += W1[f * HID + k] * W2[k * CLS + c];
        g_W[idx] = s;
    } else if (idx < FEATS * CLS + CLS) {
        int c = idx - FEATS * CLS;
        float s = b2[c];
        for (int k = 0; k < HID; k++) s += b1[k] * W2[k * CLS + c];
        g_bias[c] = s;
    }
}

// ---------------- kernel 2: Z0 = h @ W + bias (fp32) + ZT tf32 write ----------------
#define Z0_BM 64
#define Z0_BK 16
__global__ __launch_bounds__(256)
void z0_kernel(const float* __restrict__ h) {
    __shared__ float As[Z0_BM][Z0_BK + 1];
    __shared__ float Bs[Z0_BK][CLS + 1];
    int bm = blockIdx.x * Z0_BM;
    int tx = threadIdx.x % 16, ty = threadIdx.x / 16;
    float acc[4][4];
    #pragma unroll
    for (int i = 0; i < 4; i++)
        #pragma unroll
        for (int j = 0; j < 4; j++) acc[i][j] = 0.f;

    for (int k0 = 0; k0 < FEATS; k0 += Z0_BK) {
        for (int i = threadIdx.x; i < Z0_BM * Z0_BK; i += 256) {
            int r = i / Z0_BK, c = i % Z0_BK;
            As[r][c] = h[(size_t)(bm + r) * FEATS + k0 + c];
        }
        for (int i = threadIdx.x; i < Z0_BK * CLS; i += 256) {
            int r = i / CLS, c = i % CLS;
            Bs[r][c] = g_W[(k0 + r) * CLS + c];
        }
        __syncthreads();
        #pragma unroll
        for (int kk = 0; kk < Z0_BK; kk++) {
            float a[4], b[4];
            #pragma unroll
            for (int i = 0; i < 4; i++) a[i] = As[ty * 4 + i][kk];
            #pragma unroll
            for (int j = 0; j < 4; j++) b[j] = Bs[kk][tx * 4 + j];
            #pragma unroll
            for (int i = 0; i < 4; i++)
                #pragma unroll
                for (int j = 0; j < 4; j++) acc[i][j] += a[i] * b[j];
        }
        __syncthreads();
    }
    #pragma unroll
    for (int i = 0; i < 4; i++)
        #pragma unroll
        for (int j = 0; j < 4; j++) {
            int r = bm + ty * 4 + i, c = tx * 4 + j;
            float y = acc[i][j] + g_bias[c];
            g_Z0[(size_t)r * CLS + c] = y;
            g_ZT[0][c * N_ROWS + r] = f2tf32(y);
        }
}

// ---------------- kernel 3: adj -> tf32 bits (one pass) ----------------
__global__ __launch_bounds__(256)
void cvt_adj_kernel(const float* __restrict__ adj) {
    size_t base = ((size_t)blockIdx.x * 256 + threadIdx.x) * 8;
    const float4* src = (const float4*)(adj + base);
    float4 v0 = src[0], v1 = src[1];
    float f[8] = {v0.x, v0.y, v0.z, v0.w, v1.x, v1.y, v1.z, v1.w};
    uint32_t o[8];
    #pragma unroll
    for (int i = 0; i < 8; i++) o[i] = f2tf32(f[i]);
    uint4* dst = (uint4*)(g_adj32 + base);
    dst[0] = *(uint4*)(o);
    dst[1] = *(uint4*)(o + 4);
}

// ---------------- kernel 4: propagation (tf32 mma, ldmatrix, short-chain reacc) ----------------
#define BM 128
#define BN 64
#define BK 32
#define KT (N_ROWS / BK)      // 512
#define STAGES 3
#define TPB 512
#define ROW_W 36              // uint32 per smem row: 32 data + 4 pad (144B; (r+2kk)&7 distinct)
#define ASZ (BM * ROW_W)      // 4608 words / stage
#define BSZ (CLS * ROW_W)     // 2304 words / stage
#define STAGE_W (ASZ + BSZ)
#define SMEM_BYTES (STAGES * STAGE_W * 4)   // 82944

__device__ __forceinline__ void cp_async16(void* smem, const void* gmem) {
    uint32_t s = (uint32_t)__cvta_generic_to_shared(smem);
    asm volatile("cp.async.cg.shared.global [%0], [%1], 16;\n" :: "r"(s), "l"(gmem));
}
__device__ __forceinline__ void ldmatrix_x4(uint32_t& r0, uint32_t& r1,
                                            uint32_t& r2, uint32_t& r3, const void* p) {
    uint32_t a = (uint32_t)__cvta_generic_to_shared(p);
    asm volatile("ldmatrix.sync.aligned.m8n8.x4.shared.b16 {%0,%1,%2,%3}, [%4];\n"
                 : "=r"(r0), "=r"(r1), "=r"(r2), "=r"(r3) : "r"(a));
}
__device__ __forceinline__ void mma_tf32(float c[4],
                                         uint32_t a0, uint32_t a1, uint32_t a2, uint32_t a3,
                                         uint32_t b0, uint32_t b1) {
    asm volatile(
        "mma.sync.aligned.m16n8k8.row.col.f32.tf32.tf32.f32 "
        "{%0,%1,%2,%3}, {%4,%5,%6,%7}, {%8,%9}, {%0,%1,%2,%3};\n"
        : "+f"(c[0]), "+f"(c[1]), "+f"(c[2]), "+f"(c[3])
        : "r"(a0), "r"(a1), "r"(a2), "r"(a3), "r"(b0), "r"(b1));
}

__global__ __launch_bounds__(TPB, 1)
void prop_kernel(int it) {
    const int rb = it & 1, wb = rb ^ 1;
    const uint32_t* ZTin = g_ZT[rb];

    extern __shared__ uint32_t sm[];

    const int tid   = threadIdx.x;
    const int lane  = tid & 31;
    const int warp  = tid >> 5;        // 0..15
    const int warpM = warp & 3;        // 32-row slice
    const int warpN = warp >> 2;       // 16-col slice
    const int bm    = blockIdx.x * BM;
    const int lr    = lane & 7;        // row within ldmatrix group
    const int lg    = lane >> 3;       // ldmatrix group 0..3

    auto load_tiles = [&](int s, int k0) {
        uint32_t* As = sm + s * STAGE_W;
        uint32_t* Bs = As + ASZ;
        #pragma unroll
        for (int j = 0; j < 2; j++) {              // A: 128 rows x 8 chunks of 16B
            int i = tid + j * TPB;
            int r = i >> 3, c4 = (i & 7) * 4;
            cp_async16(As + r * ROW_W + c4,
                       g_adj32 + (size_t)(bm + r) * N_ROWS + k0 + c4);
        }
        {                                          // B: 64 c-rows x 8 chunks of 16B
            int c = tid >> 3, c4 = (tid & 7) * 4;
            cp_async16(Bs + c * ROW_W + c4,
                       ZTin + (size_t)c * N_ROWS + k0 + c4);
        }
        asm volatile("cp.async.commit_group;\n");
    };

    float acc[2][2][4];
    #pragma unroll
    for (int mt = 0; mt < 2; mt++)
        #pragma unroll
        for (int nt = 0; nt < 2; nt++)
            #pragma unroll
            for (int i = 0; i < 4; i++) acc[mt][nt][i] = 0.f;

    load_tiles(0, 0);
    load_tiles(1, BK);

    for (int kt = 0; kt < KT; kt++) {
        asm volatile("cp.async.wait_group 1;\n");
        __syncthreads();

        int nk = kt + 2;
        if (nk < KT) load_tiles(nk % STAGES, nk * BK);
        else         asm volatile("cp.async.commit_group;\n");

        const uint32_t* As = sm + (kt % STAGES) * STAGE_W;
        const uint32_t* Bs = As + ASZ;

        float ctile[2][2][4];
        #pragma unroll
        for (int mt = 0; mt < 2; mt++)
            #pragma unroll
            for (int nt = 0; nt < 2; nt++)
                #pragma unroll
                for (int i = 0; i < 4; i++) ctile[mt][nt][i] = 0.f;

        #pragma unroll
        for (int kk = 0; kk < 4; kk++) {
            // A fragments via ldmatrix.x4 (tf32-as-2xb16):
            // group g: row += (g&1)*8, koff += (g>>1)*4 words
            uint32_t a[2][4];
            #pragma unroll
            for (int mt = 0; mt < 2; mt++) {
                int row = warpM * 32 + mt * 16 + lr + (lg & 1) * 8;
                const uint32_t* p = As + row * ROW_W + kk * 8 + (lg >> 1) * 4;
                ldmatrix_x4(a[mt][0], a[mt][1], a[mt][2], a[mt][3], p);
            }
            // B fragments: one x4 covers nt=0,1 (b0,b1 each)
            // group g: c += (g>>1)*8, koff += (g&1)*4 words
            uint32_t b0, b1, b2, b3;
            {
                int c = warpN * 16 + lr + (lg >> 1) * 8;
                const uint32_t* p = Bs + c * ROW_W + kk * 8 + (lg & 1) * 4;
                ldmatrix_x4(b0, b1, b2, b3, p);
            }
            #pragma unroll
            for (int mt = 0; mt < 2; mt++) {
                mma_tf32(ctile[mt][0], a[mt][0], a[mt][1], a[mt][2], a[mt][3], b0, b1);
                mma_tf32(ctile[mt][1], a[mt][0], a[mt][1], a[mt][2], a[mt][3], b2, b3);
            }
        }

        #pragma unroll
        for (int mt = 0; mt < 2; mt++)
            #pragma unroll
            for (int nt = 0; nt < 2; nt++)
                #pragma unroll
                for (int i = 0; i < 4; i++) acc[mt][nt][i] += ctile[mt][nt][i];
    }

    // epilogue: y = 0.9*acc + 0.1*Z0 ; ZT[wb] tf32 always, fp32 at last iter
    #pragma unroll
    for (int mt = 0; mt < 2; mt++) {
        #pragma unroll
        for (int nt = 0; nt < 2; nt++) {
            int r0 = bm + warpM * 32 + mt * 16 + (lane >> 2);
            int c0 = warpN * 16 + nt * 8 + (lane & 3) * 2;
            #pragma unroll
            for (int i = 0; i < 4; i++) {
                int r = r0 + ((i >= 2) ? 8 : 0);
                int c = c0 + (i & 1);
                size_t idx = (size_t)r * CLS + c;
                float y = 0.9f * acc[mt][nt][i] + 0.1f * g_Z0[idx];
                g_ZT[wb][c * N_ROWS + r] = f2tf32(y);
                if (it == NITER - 1) g_Zfinal[idx] = y;
            }
        }
    }
}

// ---------------- kernel 5: row-wise log_softmax ----------------
__global__ __launch_bounds__(256)
void lsm_kernel(float* __restrict__ out) {
    int row  = blockIdx.x * 8 + (threadIdx.x >> 5);
    int lane = threadIdx.x & 31;
    const float* zr = g_Zfinal + (size_t)row * CLS;
    float v0 = zr[lane], v1 = zr[lane + 32];
    float m = fmaxf(v0, v1);
    #pragma unroll
    for (int o = 16; o > 0; o >>= 1) m = fmaxf(m, __shfl_xor_sync(0xffffffffu, m, o));
    float e = expf(v0 - m) + expf(v1 - m);
    #pragma unroll
    for (int o = 16; o > 0; o >>= 1) e += __shfl_xor_sync(0xffffffffu, e, o);
    float l = m + logf(e);
    out[(size_t)row * CLS + lane]      = v0 - l;
    out[(size_t)row * CLS + lane + 32] = v1 - l;
}

// ---------------- launch ----------------
extern "C" void kernel_launch(void* const* d_in, const int* in_sizes, int n_in,
                              void* d_out, int out_size) {
    const float *h = nullptr, *adj = nullptr, *W1 = nullptr,
                *b1 = nullptr, *W2 = nullptr, *b2 = nullptr;
    for (int i = 0; i < n_in; i++) {
        switch (in_sizes[i]) {
            case N_ROWS * FEATS:  h   = (const float*)d_in[i]; break;
            case 268435456:       adj = (const float*)d_in[i]; break;
            case FEATS * HID:     W1  = (const float*)d_in[i]; break;
            case HID:             b1  = (const float*)d_in[i]; break;
            case HID * CLS:       W2  = (const float*)d_in[i]; break;
            case CLS:             b2  = (const float*)d_in[i]; break;
            default: break;
        }
    }

    cudaFuncSetAttribute(prop_kernel, cudaFuncAttributeMaxDynamicSharedMemorySize,
                         SMEM_BYTES);

    fuse_w_kernel<<<(FEATS * CLS + CLS + 255) / 256, 256>>>(W1, b1, W2, b2);
    z0_kernel<<<N_ROWS / Z0_BM, 256>>>(h);
    cvt_adj_kernel<<<(int)(((size_t)N_ROWS * N_ROWS) / (256 * 8)), 256>>>(adj);
    for (int it = 0; it < NITER; it++)
        prop_kernel<<<N_ROWS / BM, TPB, SMEM_BYTES>>>(it);
    lsm_kernel<<<N_ROWS / 8, 256>>>((float*)d_out);
}

// round 9
// speedup vs baseline: 1.1645x; 1.1645x over previous
#include <cuda_runtime.h>
#include <cstdint>

#define N_ROWS 16384
#define FEATS  512
#define HID    256
#define CLS    64
#define NITER  10

// ---------------- scratch ----------------
__device__ float g_W[FEATS * CLS];
__device__ float g_bias[CLS];
__device__ float g_Z0[N_ROWS * CLS];
__device__ float g_Zfinal[N_ROWS * CLS];
__device__ uint32_t g_ZT[2][CLS * N_ROWS];   // Z^T [class][node], tf32 bits

__device__ __forceinline__ uint32_t f2tf32(float f) {
    uint32_t u;
    asm volatile("cvt.rna.tf32.f32 %0, %1;\n" : "=r"(u) : "f"(f));
    return u;
}
__device__ __forceinline__ uint32_t cvt_reg_tf32(uint32_t v) {
    uint32_t u;
    asm volatile("cvt.rna.tf32.f32 %0, %1;\n" : "=r"(u) : "f"(__uint_as_float(v)));
    return u;
}
__device__ __forceinline__ uint32_t smem_u32_of(const void* p) {
    uint32_t a;
    asm("{ .reg .u64 t; cvta.to.shared.u64 t, %1; cvt.u32.u64 %0, t; }" : "=r"(a) : "l"(p));
    return a;
}
__device__ __forceinline__ void cp_async16(uint32_t smem, const void* gmem) {
    asm volatile("cp.async.cg.shared.global [%0], [%1], 16;\n" :: "r"(smem), "l"(gmem));
}
__device__ __forceinline__ void ldmatrix_x4(uint32_t& r0, uint32_t& r1,
                                            uint32_t& r2, uint32_t& r3, uint32_t a) {
    asm volatile("ldmatrix.sync.aligned.m8n8.x4.shared.b16 {%0,%1,%2,%3}, [%4];\n"
                 : "=r"(r0), "=r"(r1), "=r"(r2), "=r"(r3) : "r"(a));
}
__device__ __forceinline__ void mma_tf32(float c[4],
                                         uint32_t a0, uint32_t a1, uint32_t a2, uint32_t a3,
                                         uint32_t b0, uint32_t b1) {
    asm volatile(
        "mma.sync.aligned.m16n8k8.row.col.f32.tf32.tf32.f32 "
        "{%0,%1,%2,%3}, {%4,%5,%6,%7}, {%8,%9}, {%0,%1,%2,%3};\n"
        : "+f"(c[0]), "+f"(c[1]), "+f"(c[2]), "+f"(c[3])
        : "r"(a0), "r"(a1), "r"(a2), "r"(a3), "r"(b0), "r"(b1));
}

// ---------------- kernel 1: collapse the MLP ----------------
__global__ void fuse_w_kernel(const float* __restrict__ W1, const float* __restrict__ b1,
                              const float* __restrict__ W2, const float* __restrict__ b2) {
    int idx = blockIdx.x * blockDim.x + threadIdx.x;
    if (idx < FEATS * CLS) {
        int f = idx / CLS, c = idx % CLS;
        float s = 0.f;
        #pragma unroll 8
        for (int k = 0; k < HID; k++) s += W1[f * HID + k] * W2[k * CLS + c];
        g_W[idx] = s;
    } else if (idx < FEATS * CLS + CLS) {
        int c = idx - FEATS * CLS;
        float s = b2[c];
        for (int k = 0; k < HID; k++) s += b1[k] * W2[k * CLS + c];
        g_bias[c] = s;
    }
}

// ---------------- kernel 2: Z0 = h @ W + bias ----------------
#define Z0_BM 64
#define Z0_BK 16
__global__ __launch_bounds__(256)
void z0_kernel(const float* __restrict__ h) {
    __shared__ float As[Z0_BM][Z0_BK + 1];
    __shared__ float Bs[Z0_BK][CLS + 1];
    int bm = blockIdx.x * Z0_BM;
    int tx = threadIdx.x % 16, ty = threadIdx.x / 16;
    float acc[4][4];
    #pragma unroll
    for (int i = 0; i < 4; i++)
        #pragma unroll
        for (int j = 0; j < 4; j++) acc[i][j] = 0.f;

    for (int k0 = 0; k0 < FEATS; k0 += Z0_BK) {
        for (int i = threadIdx.x; i < Z0_BM * Z0_BK; i += 256) {
            int r = i / Z0_BK, c = i % Z0_BK;
            As[r][c] = h[(size_t)(bm + r) * FEATS + k0 + c];
        }
        for (int i = threadIdx.x; i < Z0_BK * CLS; i += 256) {
            int r = i / CLS, c = i % CLS;
            Bs[r][c] = g_W[(k0 + r) * CLS + c];
        }
        __syncthreads();
        #pragma unroll
        for (int kk = 0; kk < Z0_BK; kk++) {
            float a[4], b[4];
            #pragma unroll
            for (int i = 0; i < 4; i++) a[i] = As[ty * 4 + i][kk];
            #pragma unroll
            for (int j = 0; j < 4; j++) b[j] = Bs[kk][tx * 4 + j];
            #pragma unroll
            for (int i = 0; i < 4; i++)
                #pragma unroll
                for (int j = 0; j < 4; j++) acc[i][j] += a[i] * b[j];
        }
        __syncthreads();
    }
    #pragma unroll
    for (int i = 0; i < 4; i++)
        #pragma unroll
        for (int j = 0; j < 4; j++) {
            int r = bm + ty * 4 + i, c = tx * 4 + j;
            float y = acc[i][j] + g_bias[c];
            g_Z0[(size_t)r * CLS + c] = y;
            g_ZT[0][c * N_ROWS + r] = f2tf32(y);
        }
}

// ---------------- kernel 3: propagation (mma.sync tf32, 8 warps, ldmatrix) ----------------
#define BM 128
#define SBK 64                 // k per stage (2 logical 32-k tiles)
#define NST (N_ROWS / SBK)     // 256 stages
#define STAGES 3
#define ROW_W 68               // words/row: 64 data + 4 pad; (4r+c)&31 distinct over 8 rows
#define ASZ (BM * ROW_W)       // 8704 words
#define BSZ (CLS * ROW_W)      // 4352 words
#define STAGE_W (ASZ + BSZ)    // 13056 words
#define SMEM_BYTES (STAGES * STAGE_W * 4)   // 156672

__global__ __launch_bounds__(256, 1)
void prop_kernel(const float* __restrict__ adj, int it) {
    const int rb = it & 1, wb = rb ^ 1;
    const uint32_t* ZTin = g_ZT[rb];

    extern __shared__ uint32_t sm[];
    const uint32_t smem0 = smem_u32_of(sm);

    const int tid   = threadIdx.x;
    const int lane  = tid & 31;
    const int warp  = tid >> 5;
    const int warpM = warp >> 1;        // 0..3, 32 rows each
    const int warpN = warp & 1;         // 0..1, 32 cols each
    const int bm    = blockIdx.x * BM;
    const int lr    = lane & 7;
    const int lg    = lane >> 3;

    auto load_stage = [&](int s, int st) {
        const int k0 = st * SBK;
        const uint32_t base = smem0 + (s * STAGE_W) * 4;
        #pragma unroll
        for (int j = 0; j < 8; j++) {          // A: 128 rows x 16 float4
            int ch = tid + j * 256;
            int r = ch >> 4, c4 = (ch & 15) * 4;
            cp_async16(base + (r * ROW_W + c4) * 4,
                       adj + (size_t)(bm + r) * N_ROWS + k0 + c4);
        }
        #pragma unroll
        for (int j = 0; j < 4; j++) {          // B: 64 class-rows x 16 float4
            int ch = tid + j * 256;
            int n = ch >> 4, c4 = (ch & 15) * 4;
            cp_async16(base + (ASZ + n * ROW_W + c4) * 4,
                       ZTin + (size_t)n * N_ROWS + k0 + c4);
        }
        asm volatile("cp.async.commit_group;\n");
    };

    float acc[2][4][4];
    #pragma unroll
    for (int mt = 0; mt < 2; mt++)
        #pragma unroll
        for (int nt = 0; nt < 4; nt++)
            #pragma unroll
            for (int i = 0; i < 4; i++) acc[mt][nt][i] = 0.f;

    load_stage(0, 0);
    load_stage(1, 1);

    // precomputed fragment base addresses (bytes)
    const uint32_t a_row0 = warpM * 32 + lr + (lg & 1) * 8;   // + mt*16
    const uint32_t a_koff = (lg >> 1) * 4;                    // + half*32 + kk*8
    const uint32_t b_row0 = warpN * 32 + lr + (lg >> 1) * 8;  // + ntp*16
    const uint32_t b_koff = (lg & 1) * 4;

    for (int st = 0; st < NST; st++) {
        asm volatile("cp.async.wait_group 1;\n");
        __syncthreads();

        int ns = st + 2;
        if (ns < NST) load_stage(ns % STAGES, ns);
        else          asm volatile("cp.async.commit_group;\n");

        const uint32_t base = smem0 + ((st % STAGES) * STAGE_W) * 4;

        #pragma unroll
        for (int half = 0; half < 2; half++) {
            float ctile[2][4][4];
            #pragma unroll
            for (int mt = 0; mt < 2; mt++)
                #pragma unroll
                for (int nt = 0; nt < 4; nt++)
                    #pragma unroll
                    for (int i = 0; i < 4; i++) ctile[mt][nt][i] = 0.f;

            #pragma unroll
            for (int kk = 0; kk < 4; kk++) {
                const uint32_t koff = half * 32 + kk * 8;
                uint32_t a[2][4];
                #pragma unroll
                for (int mt = 0; mt < 2; mt++) {
                    ldmatrix_x4(a[mt][0], a[mt][1], a[mt][2], a[mt][3],
                                base + ((a_row0 + mt * 16) * ROW_W + koff + a_koff) * 4);
                    #pragma unroll
                    for (int q = 0; q < 4; q++) a[mt][q] = cvt_reg_tf32(a[mt][q]);
                }
                #pragma unroll
                for (int ntp = 0; ntp < 2; ntp++) {
                    uint32_t b0, b1, b2, b3;
                    ldmatrix_x4(b0, b1, b2, b3,
                                base + (ASZ + (b_row0 + ntp * 16) * ROW_W + koff + b_koff) * 4);
                    #pragma unroll
                    for (int mt = 0; mt < 2; mt++) {
                        mma_tf32(ctile[mt][ntp * 2],     a[mt][0], a[mt][1], a[mt][2], a[mt][3], b0, b1);
                        mma_tf32(ctile[mt][ntp * 2 + 1], a[mt][0], a[mt][1], a[mt][2], a[mt][3], b2, b3);
                    }
                }
            }
            #pragma unroll
            for (int mt = 0; mt < 2; mt++)
                #pragma unroll
                for (int nt = 0; nt < 4; nt++)
                    #pragma unroll
                    for (int i = 0; i < 4; i++) acc[mt][nt][i] += ctile[mt][nt][i];
        }
    }

    // epilogue: y = 0.9*acc + 0.1*Z0 ; ZT tf32 always; fp32 at last iter
    #pragma unroll
    for (int mt = 0; mt < 2; mt++) {
        #pragma unroll
        for (int nt = 0; nt < 4; nt++) {
            int r0 = bm + warpM * 32 + mt * 16 + (lane >> 2);
            int c0 = warpN * 32 + (nt >> 1) * 16 + (nt & 1) * 8 + (lane & 3) * 2;
            #pragma unroll
            for (int i = 0; i < 4; i++) {
                int r = r0 + ((i >= 2) ? 8 : 0);
                int c = c0 + (i & 1);
                size_t idx = (size_t)r * CLS + c;
                float y = 0.9f * acc[mt][nt][i] + 0.1f * g_Z0[idx];
                g_ZT[wb][c * N_ROWS + r] = f2tf32(y);
                if (it == NITER - 1) g_Zfinal[idx] = y;
            }
        }
    }
}

// ---------------- kernel 4: log_softmax ----------------
__global__ __launch_bounds__(256)
void lsm_kernel(float* __restrict__ out) {
    int row  = blockIdx.x * 8 + (threadIdx.x >> 5);
    int lane = threadIdx.x & 31;
    const float* zr = g_Zfinal + (size_t)row * CLS;
    float v0 = zr[lane], v1 = zr[lane + 32];
    float m = fmaxf(v0, v1);
    #pragma unroll
    for (int o = 16; o > 0; o >>= 1) m = fmaxf(m, __shfl_xor_sync(0xffffffffu, m, o));
    float e = expf(v0 - m) + expf(v1 - m);
    #pragma unroll
    for (int o = 16; o > 0; o >>= 1) e += __shfl_xor_sync(0xffffffffu, e, o);
    float l = m + logf(e);
    out[(size_t)row * CLS + lane]      = v0 - l;
    out[(size_t)row * CLS + lane + 32] = v1 - l;
}

// ---------------- launch ----------------
extern "C" void kernel_launch(void* const* d_in, const int* in_sizes, int n_in,
                              void* d_out, int out_size) {
    const float *h = nullptr, *adj = nullptr, *W1 = nullptr,
                *b1 = nullptr, *W2 = nullptr, *b2 = nullptr;
    for (int i = 0; i < n_in; i++) {
        switch (in_sizes[i]) {
            case N_ROWS * FEATS:  h   = (const float*)d_in[i]; break;
            case 268435456:       adj = (const float*)d_in[i]; break;
            case FEATS * HID:     W1  = (const float*)d_in[i]; break;
            case HID:             b1  = (const float*)d_in[i]; break;
            case HID * CLS:       W2  = (const float*)d_in[i]; break;
            case CLS:             b2  = (const float*)d_in[i]; break;
            default: break;
        }
    }

    cudaFuncSetAttribute(prop_kernel, cudaFuncAttributeMaxDynamicSharedMemorySize,
                         SMEM_BYTES);

    fuse_w_kernel<<<(FEATS * CLS + CLS + 255) / 256, 256>>>(W1, b1, W2, b2);
    z0_kernel<<<N_ROWS / Z0_BM, 256>>>(h);
    for (int it = 0; it < NITER; it++)
        prop_kernel<<<N_ROWS / BM, 256, SMEM_BYTES>>>(adj, it);
    lsm_kernel<<<N_ROWS / 8, 256>>>((float*)d_out);
}